// round 2
// baseline (speedup 1.0000x reference)
#include <cuda_runtime.h>
#include <float.h>
#include <stdint.h>

// ---------------------------------------------------------------------------
// Problem constants
// ---------------------------------------------------------------------------
#define BATCH   8
#define NP      4224          // padded sequence (128 text + 4096 image)
#define NSEQ    4223          // real sequence length
#define TEXTL   128
#define IMGDIM  64            // 64x64 image grid
#define NHEAD   16
#define DHEAD   64
#define DIMC    1024
#define TRIPLE  3072
#define MROWS   (BATCH*NP)    // 33792

// Scratch (device globals — no allocation allowed)
__device__ float   g_qkv [(size_t)BATCH * NP * TRIPLE];  // q|k|v, 415 MB
__device__ float   g_attn[(size_t)BATCH * NP * DIMC];    // attention output, 138 MB
__device__ uint8_t g_mask[BATCH * TEXTL];                // normalized mask

// ---------------------------------------------------------------------------
// Mask normalization: the harness may deliver the bool mask as int32, float32,
// or uint8. Classify by inspecting the first 1024 bytes (safe to read under
// every hypothesis: the smallest possible buffer is 1024 bytes), then expand
// into g_mask as clean 0/1 bytes.
// ---------------------------------------------------------------------------
__global__ void normalize_mask_kernel(const void* __restrict__ mask_raw)
{
    __shared__ int cls;   // 0 = word-sized (int32/float32), 1 = uint8
    const uint32_t* w = (const uint32_t*)mask_raw;
    const uint8_t*  c = (const uint8_t*)mask_raw;

    if (threadIdx.x == 0) {
        bool all_int = true, all_f32 = true;
        for (int i = 0; i < 256; i++) {          // first 1024 bytes as words
            uint32_t v = w[i];
            if (v != 0u && v != 1u)           all_int = false;
            if (v != 0u && v != 0x3F800000u)  all_f32 = false;
        }
        cls = (all_int || all_f32) ? 0 : 1;
    }
    __syncthreads();

    for (int i = threadIdx.x; i < BATCH * TEXTL; i += blockDim.x) {
        uint8_t m;
        if (cls == 0) m = (w[i] != 0u) ? 1 : 0;   // int32 or float32 storage
        else          m = (c[i] != 0u) ? 1 : 0;   // byte storage
        g_mask[i] = m;
    }
}

// ---------------------------------------------------------------------------
// GEMM1: qkv = pad(x) @ w_qkv    [33792,1024] x [1024,3072]
// 128x128 tile, BK=16, 256 threads, 8x8 per thread.
// Padded row (t == NSEQ within each batch) is zero-filled.
// ---------------------------------------------------------------------------
__global__ __launch_bounds__(256) void gemm_qkv_kernel(
    const float* __restrict__ x, const float* __restrict__ w)
{
    __shared__ float As[16][128];
    __shared__ float Bs[16][128];
    const int bn  = blockIdx.x;   // N tile (24)
    const int bm  = blockIdx.y;   // M tile (264)
    const int tid = threadIdx.x;
    const int ty  = tid >> 4, tx = tid & 15;

    float acc[8][8];
#pragma unroll
    for (int i = 0; i < 8; i++)
#pragma unroll
        for (int j = 0; j < 8; j++) acc[i][j] = 0.f;

    for (int k0 = 0; k0 < DIMC; k0 += 16) {
        // A tile: 128 rows x 16 cols, transposed into As[k][m]
#pragma unroll
        for (int l = 0; l < 2; l++) {
            int idx = tid + l * 256;          // 0..511 float4 slots
            int r   = idx >> 2;               // row in tile
            int c4  = idx & 3;                // float4 within 16 cols
            int m   = bm * 128 + r;
            int b   = m / NP, t = m - b * NP;
            float4 v = make_float4(0.f, 0.f, 0.f, 0.f);
            if (t < NSEQ)
                v = *(const float4*)&x[((size_t)(b * NSEQ + t)) * DIMC + k0 + c4 * 4];
            As[c4*4+0][r] = v.x; As[c4*4+1][r] = v.y;
            As[c4*4+2][r] = v.z; As[c4*4+3][r] = v.w;
        }
        // B tile: 16 rows x 128 cols
#pragma unroll
        for (int l = 0; l < 2; l++) {
            int idx = tid + l * 256;
            int kk  = idx >> 5;               // 0..15
            int c4  = idx & 31;               // float4 col
            *(float4*)&Bs[kk][c4*4] =
                *(const float4*)&w[(size_t)(k0 + kk) * TRIPLE + bn * 128 + c4 * 4];
        }
        __syncthreads();
#pragma unroll
        for (int kk = 0; kk < 16; kk++) {
            float a[8], bb[8];
            *(float4*)&a[0]  = *(const float4*)&As[kk][ty*8];
            *(float4*)&a[4]  = *(const float4*)&As[kk][ty*8+4];
            *(float4*)&bb[0] = *(const float4*)&Bs[kk][tx*8];
            *(float4*)&bb[4] = *(const float4*)&Bs[kk][tx*8+4];
#pragma unroll
            for (int i = 0; i < 8; i++)
#pragma unroll
                for (int j = 0; j < 8; j++) acc[i][j] += a[i] * bb[j];
        }
        __syncthreads();
    }
#pragma unroll
    for (int i = 0; i < 8; i++) {
        int m = bm * 128 + ty * 8 + i;
        float* row = &g_qkv[(size_t)m * TRIPLE + bn * 128 + tx * 8];
        *(float4*)&row[0] = make_float4(acc[i][0], acc[i][1], acc[i][2], acc[i][3]);
        *(float4*)&row[4] = make_float4(acc[i][4], acc[i][5], acc[i][6], acc[i][7]);
    }
}

// ---------------------------------------------------------------------------
// GEMM2: out = g_attn @ w_out    [33792,1024] x [1024,1024]
// Same tiling; store drops the padded row and re-indexes to length-4223 rows.
// ---------------------------------------------------------------------------
__global__ __launch_bounds__(256) void gemm_out_kernel(
    const float* __restrict__ w, float* __restrict__ out)
{
    __shared__ float As[16][128];
    __shared__ float Bs[16][128];
    const int bn  = blockIdx.x;   // 8
    const int bm  = blockIdx.y;   // 264
    const int tid = threadIdx.x;
    const int ty  = tid >> 4, tx = tid & 15;

    float acc[8][8];
#pragma unroll
    for (int i = 0; i < 8; i++)
#pragma unroll
        for (int j = 0; j < 8; j++) acc[i][j] = 0.f;

    for (int k0 = 0; k0 < DIMC; k0 += 16) {
#pragma unroll
        for (int l = 0; l < 2; l++) {
            int idx = tid + l * 256;
            int r   = idx >> 2;
            int c4  = idx & 3;
            int m   = bm * 128 + r;
            float4 v = *(const float4*)&g_attn[(size_t)m * DIMC + k0 + c4 * 4];
            As[c4*4+0][r] = v.x; As[c4*4+1][r] = v.y;
            As[c4*4+2][r] = v.z; As[c4*4+3][r] = v.w;
        }
#pragma unroll
        for (int l = 0; l < 2; l++) {
            int idx = tid + l * 256;
            int kk  = idx >> 5;
            int c4  = idx & 31;
            *(float4*)&Bs[kk][c4*4] =
                *(const float4*)&w[(size_t)(k0 + kk) * DIMC + bn * 128 + c4 * 4];
        }
        __syncthreads();
#pragma unroll
        for (int kk = 0; kk < 16; kk++) {
            float a[8], bb[8];
            *(float4*)&a[0]  = *(const float4*)&As[kk][ty*8];
            *(float4*)&a[4]  = *(const float4*)&As[kk][ty*8+4];
            *(float4*)&bb[0] = *(const float4*)&Bs[kk][tx*8];
            *(float4*)&bb[4] = *(const float4*)&Bs[kk][tx*8+4];
#pragma unroll
            for (int i = 0; i < 8; i++)
#pragma unroll
                for (int j = 0; j < 8; j++) acc[i][j] += a[i] * bb[j];
        }
        __syncthreads();
    }
#pragma unroll
    for (int i = 0; i < 8; i++) {
        int m = bm * 128 + ty * 8 + i;
        int b = m / NP, t = m - b * NP;
        if (t < NSEQ) {
            float* row = &out[((size_t)(b * NSEQ + t)) * DIMC + bn * 128 + tx * 8];
            *(float4*)&row[0] = make_float4(acc[i][0], acc[i][1], acc[i][2], acc[i][3]);
            *(float4*)&row[4] = make_float4(acc[i][4], acc[i][5], acc[i][6], acc[i][7]);
        }
    }
}

// ---------------------------------------------------------------------------
// Text attention: per (b,h), 128 queries x 128 keys, causal.
// Block = 128 threads (one query per thread). Dyn smem: KV[128][64] + S[128][128].
// ---------------------------------------------------------------------------
__global__ __launch_bounds__(128) void text_attn_kernel()
{
    extern __shared__ float sm[];
    float* KV = sm;             // 128*64
    float* S  = sm + 128 * 64;  // 128*128

    const int bh = blockIdx.x;
    const int b  = bh / NHEAD;
    const int h  = bh - b * NHEAD;
    const int i  = threadIdx.x;

    // load K
    for (int idx = threadIdx.x; idx < 128 * 64 / 4; idx += 128) {
        int t = idx >> 4, c4 = idx & 15;
        *(float4*)&KV[t * 64 + c4 * 4] =
            *(const float4*)&g_qkv[((size_t)(b * NP + t)) * TRIPLE + DIMC + h * DHEAD + c4 * 4];
    }
    __syncthreads();

    float q[64];
    {
        const float* qp = &g_qkv[((size_t)(b * NP + i)) * TRIPLE + h * DHEAD];
#pragma unroll
        for (int d = 0; d < 64; d++) q[d] = qp[d] * 0.125f;
    }

    float mx = -FLT_MAX;
    for (int j = 0; j <= i; j++) {
        const float* kp = &KV[j * 64];
        float s0 = 0.f, s1 = 0.f, s2 = 0.f, s3 = 0.f;
#pragma unroll
        for (int d = 0; d < 64; d += 4) {
            s0 += q[d+0] * kp[d+0]; s1 += q[d+1] * kp[d+1];
            s2 += q[d+2] * kp[d+2]; s3 += q[d+3] * kp[d+3];
        }
        float s = (s0 + s1) + (s2 + s3);
        S[i * 128 + j] = s;
        mx = fmaxf(mx, s);
    }
    float sum = 0.f;
    for (int j = 0; j <= i; j++) {
        float p = __expf(S[i * 128 + j] - mx);
        S[i * 128 + j] = p;
        sum += p;
    }
    __syncthreads();  // all threads done with K

    // load V over KV
    for (int idx = threadIdx.x; idx < 128 * 64 / 4; idx += 128) {
        int t = idx >> 4, c4 = idx & 15;
        *(float4*)&KV[t * 64 + c4 * 4] =
            *(const float4*)&g_qkv[((size_t)(b * NP + t)) * TRIPLE + 2 * DIMC + h * DHEAD + c4 * 4];
    }
    __syncthreads();

    float o[64];
#pragma unroll
    for (int d = 0; d < 64; d++) o[d] = 0.f;
    for (int j = 0; j <= i; j++) {
        float p = S[i * 128 + j];
        const float* vp = &KV[j * 64];
#pragma unroll
        for (int d = 0; d < 64; d++) o[d] += p * vp[d];
    }
    float inv = 1.f / sum;
    float* op = &g_attn[((size_t)(b * NP + i)) * DIMC + h * DHEAD];
#pragma unroll
    for (int d = 0; d < 64; d++) op[d] = o[d] * inv;
}

// ---------------------------------------------------------------------------
// Image (axial) attention: per (b,h,imgrow). 64 queries attend 128 text keys
// (mask) + <=64 same-row keys (causal). Block = 64 threads, one query each.
// Dyn smem: KV[192*64] (K then reused for V) + S[64*192].
// ---------------------------------------------------------------------------
__global__ __launch_bounds__(64) void img_attn_kernel()
{
    extern __shared__ float sm[];
    float* KV = sm;              // 192*64 = 12288
    float* S  = sm + 192 * 64;   // 64*192 = 12288
    __shared__ uint8_t smask[TEXTL];

    const int bid = blockIdx.x;          // b*16*64 + h*64 + x
    const int xr  = bid & 63;
    const int h   = (bid >> 6) & 15;
    const int b   = bid >> 10;
    const int i   = threadIdx.x;         // query col within row

    // normalized mask into smem
    for (int j = threadIdx.x; j < TEXTL; j += 64) smask[j] = g_mask[b * TEXTL + j];

    // load K: 192 keys x 64
    for (int idx = threadIdx.x; idx < 192 * 64 / 4; idx += 64) {
        int r = idx >> 4, c4 = idx & 15;
        int t = (r < TEXTL) ? r : (TEXTL + xr * 64 + (r - TEXTL));
        *(float4*)&KV[r * 64 + c4 * 4] =
            *(const float4*)&g_qkv[((size_t)(b * NP + t)) * TRIPLE + DIMC + h * DHEAD + c4 * 4];
    }
    __syncthreads();

    float q[64];
    {
        const int tq = TEXTL + xr * 64 + i;
        const float* qp = &g_qkv[((size_t)(b * NP + tq)) * TRIPLE + h * DHEAD];
#pragma unroll
        for (int d = 0; d < 64; d++) q[d] = qp[d] * 0.125f;
    }

    float mx = -FLT_MAX;
    // text keys (masked)
    for (int j = 0; j < TEXTL; j++) {
        const float* kp = &KV[j * 64];
        float s0 = 0.f, s1 = 0.f, s2 = 0.f, s3 = 0.f;
#pragma unroll
        for (int d = 0; d < 64; d += 4) {
            s0 += q[d+0] * kp[d+0]; s1 += q[d+1] * kp[d+1];
            s2 += q[d+2] * kp[d+2]; s3 += q[d+3] * kp[d+3];
        }
        float s = (s0 + s1) + (s2 + s3);
        s = smask[j] ? s : -FLT_MAX;
        S[i * 192 + j] = s;
        mx = fmaxf(mx, s);
    }
    // same-row keys, causal j <= i
    for (int j = 0; j <= i; j++) {
        const float* kp = &KV[(TEXTL + j) * 64];
        float s0 = 0.f, s1 = 0.f, s2 = 0.f, s3 = 0.f;
#pragma unroll
        for (int d = 0; d < 64; d += 4) {
            s0 += q[d+0] * kp[d+0]; s1 += q[d+1] * kp[d+1];
            s2 += q[d+2] * kp[d+2]; s3 += q[d+3] * kp[d+3];
        }
        float s = (s0 + s1) + (s2 + s3);
        S[i * 192 + TEXTL + j] = s;
        mx = fmaxf(mx, s);
    }

    float sum = 0.f;
    for (int j = 0; j < TEXTL; j++) {
        float p = __expf(S[i * 192 + j] - mx);
        S[i * 192 + j] = p;
        sum += p;
    }
    for (int j = 0; j <= i; j++) {
        float p = __expf(S[i * 192 + TEXTL + j] - mx);
        S[i * 192 + TEXTL + j] = p;
        sum += p;
    }
    __syncthreads();  // done with K

    // load V over KV
    for (int idx = threadIdx.x; idx < 192 * 64 / 4; idx += 64) {
        int r = idx >> 4, c4 = idx & 15;
        int t = (r < TEXTL) ? r : (TEXTL + xr * 64 + (r - TEXTL));
        *(float4*)&KV[r * 64 + c4 * 4] =
            *(const float4*)&g_qkv[((size_t)(b * NP + t)) * TRIPLE + 2 * DIMC + h * DHEAD + c4 * 4];
    }
    __syncthreads();

    float o[64];
#pragma unroll
    for (int d = 0; d < 64; d++) o[d] = 0.f;
    for (int j = 0; j < TEXTL; j++) {
        float p = S[i * 192 + j];
        const float* vp = &KV[j * 64];
#pragma unroll
        for (int d = 0; d < 64; d++) o[d] += p * vp[d];
    }
    for (int j = 0; j <= i; j++) {
        float p = S[i * 192 + TEXTL + j];
        const float* vp = &KV[(TEXTL + j) * 64];
#pragma unroll
        for (int d = 0; d < 64; d++) o[d] += p * vp[d];
    }
    float inv = 1.f / sum;
    const int tq = TEXTL + xr * 64 + i;
    float* op = &g_attn[((size_t)(b * NP + tq)) * DIMC + h * DHEAD];
#pragma unroll
    for (int d = 0; d < 64; d++) op[d] = o[d] * inv;
}

// ---------------------------------------------------------------------------
// Launch
// ---------------------------------------------------------------------------
extern "C" void kernel_launch(void* const* d_in, const int* in_sizes, int n_in,
                              void* d_out, int out_size)
{
    // Identify inputs by element count (robust to ordering):
    //   x: 34,594,816   mask: 1,024   w_qkv: 3,145,728   w_out: 1,048,576
    const float* x     = nullptr;
    const void*  mask  = nullptr;
    const float* w_qkv = nullptr;
    const float* w_out = nullptr;
    for (int i = 0; i < n_in; i++) {
        long long sz = in_sizes[i];
        if      (sz == (long long)BATCH * NSEQ * DIMC) x     = (const float*)d_in[i];
        else if (sz == BATCH * TEXTL)                  mask  = d_in[i];
        else if (sz == (long long)DIMC * TRIPLE)       w_qkv = (const float*)d_in[i];
        else if (sz == (long long)DIMC * DIMC)         w_out = (const float*)d_in[i];
    }
    float* out = (float*)d_out;

    const int SMEM_ATT = 98304;  // 24576 floats
    cudaFuncSetAttribute(text_attn_kernel, cudaFuncAttributeMaxDynamicSharedMemorySize, SMEM_ATT);
    cudaFuncSetAttribute(img_attn_kernel,  cudaFuncAttributeMaxDynamicSharedMemorySize, SMEM_ATT);

    normalize_mask_kernel<<<1, 256>>>(mask);

    dim3 g1(TRIPLE / 128, MROWS / 128);  // 24 x 264
    gemm_qkv_kernel<<<g1, 256>>>(x, w_qkv);

    text_attn_kernel<<<BATCH * NHEAD, 128, SMEM_ATT>>>();
    img_attn_kernel<<<BATCH * NHEAD * IMGDIM, 64, SMEM_ATT>>>();

    dim3 g2(DIMC / 128, MROWS / 128);    // 8 x 264
    gemm_out_kernel<<<g2, 256>>>(w_out, out);
}

// round 4
// speedup vs baseline: 1.6410x; 1.6410x over previous
#include <cuda_runtime.h>
#include <cuda_bf16.h>
#include <float.h>
#include <stdint.h>

// ---------------------------------------------------------------------------
// Problem constants
// ---------------------------------------------------------------------------
#define BATCH   8
#define NP      4224
#define NSEQ    4223
#define TEXTL   128
#define IMGDIM  64
#define NHEAD   16
#define DHEAD   64
#define DIMC    1024
#define TRIPLE  3072
#define MROWS   (BATCH*NP)    // 33792
#define KTOT    1024
#define BK      32
#define NCHUNK  (KTOT / BK)

// Scratch (device globals — no allocation allowed)
__device__ float   g_qkv   [(size_t)BATCH * NP * TRIPLE];
__device__ float   g_attn  [(size_t)BATCH * NP * DIMC];
__device__ float   g_wt_qkv[(size_t)TRIPLE * DIMC];   // w_qkv^T  [3072][1024]
__device__ float   g_wt_out[(size_t)DIMC * DIMC];     // w_out^T  [1024][1024]
__device__ uint8_t g_mask  [BATCH * TEXTL];

// ---------------------------------------------------------------------------
// warp mma.sync bf16 (baseline PTX, works on compute_103)
// ---------------------------------------------------------------------------
__device__ __forceinline__ void mma16816(float d[4], const uint32_t a[4], const uint32_t b[2])
{
    asm volatile(
        "mma.sync.aligned.m16n8k16.row.col.f32.bf16.bf16.f32 "
        "{%0,%1,%2,%3},{%4,%5,%6,%7},{%8,%9},{%0,%1,%2,%3};\n"
        : "+f"(d[0]), "+f"(d[1]), "+f"(d[2]), "+f"(d[3])
        : "r"(a[0]), "r"(a[1]), "r"(a[2]), "r"(a[3]), "r"(b[0]), "r"(b[1]));
}

__device__ __forceinline__ uint32_t pack_bf16(__nv_bfloat16 x, __nv_bfloat16 y)
{
    __nv_bfloat162 p = __halves2bfloat162(x, y);
    return *(uint32_t*)&p;
}

// ---------------------------------------------------------------------------
// Mask normalization (bool mask may arrive as int32 / float32 / uint8)
// ---------------------------------------------------------------------------
__global__ void normalize_mask_kernel(const void* __restrict__ mask_raw)
{
    __shared__ int cls;
    const uint32_t* w = (const uint32_t*)mask_raw;
    const uint8_t*  c = (const uint8_t*)mask_raw;
    if (threadIdx.x == 0) {
        bool all_int = true, all_f32 = true;
        for (int i = 0; i < 256; i++) {
            uint32_t v = w[i];
            if (v != 0u && v != 1u)          all_int = false;
            if (v != 0u && v != 0x3F800000u) all_f32 = false;
        }
        cls = (all_int || all_f32) ? 0 : 1;
    }
    __syncthreads();
    for (int i = threadIdx.x; i < BATCH * TEXTL; i += blockDim.x)
        g_mask[i] = (cls == 0) ? (w[i] != 0u) : (c[i] != 0u);
}

// ---------------------------------------------------------------------------
// Transpose: dst[C][R] = src[R][C]
// ---------------------------------------------------------------------------
__global__ __launch_bounds__(256) void transpose_kernel(
    const float* __restrict__ src, float* __restrict__ dst, int R, int C)
{
    __shared__ float tile[32][33];
    int c0 = blockIdx.x * 32, r0 = blockIdx.y * 32;
    int x = threadIdx.x, y = threadIdx.y;
#pragma unroll
    for (int i = 0; i < 32; i += 8)
        tile[y + i][x] = src[(size_t)(r0 + y + i) * C + c0 + x];
    __syncthreads();
#pragma unroll
    for (int i = 0; i < 32; i += 8)
        dst[(size_t)(c0 + y + i) * R + r0 + x] = tile[x][y + i];
}

// ---------------------------------------------------------------------------
// bf16x3 tensor-core GEMM:  C[M,N] = A[M,1024] @ Bt[N,1024]^T
// CTA 128x128, BK=32, 8 warps (2x4), warp tile 64x32 via m16n8k16.
// A,B split fp32 -> (hi,lo) bf16; D += Ah*Bh + Ah*Bl + Al*Bh.
// SMEM rows padded to 40 bf16 (stride 20 banks -> conflict-free frag loads).
// ---------------------------------------------------------------------------
#define LSTRIDE 40
#define MAT_ELEMS (128 * LSTRIDE)                 // 5120 bf16 per matrix
#define STAGE_ELEMS (4 * MAT_ELEMS)               // Ah,Al,Bh,Bl
#define SMEM_GEMM (2 * STAGE_ELEMS * 2)           // bytes: 81920

template <int NSTRIDE, bool PAD_A, bool TRIM>
__global__ __launch_bounds__(256)
void gemm_mma_kernel(const float* __restrict__ A, const float* __restrict__ Bt,
                     float* __restrict__ C)
{
    extern __shared__ __nv_bfloat16 sm[];
    const int tid  = threadIdx.x;
    const int bn   = blockIdx.x;
    const int bm   = blockIdx.y;
    const int warp = tid >> 5;
    const int lane = tid & 31;
    const int wm   = warp >> 2;       // 0..1 -> m offset 0/64
    const int wn   = warp & 3;        // 0..3 -> n offset 0/32/64/96
    const int g    = lane >> 2;       // 0..7
    const int t4   = lane & 3;        // 0..3

    float acc[4][4][4];
#pragma unroll
    for (int mi = 0; mi < 4; mi++)
#pragma unroll
        for (int ni = 0; ni < 4; ni++)
#pragma unroll
            for (int r = 0; r < 4; r++) acc[mi][ni][r] = 0.f;

    float4 ra[4], rb[4];

    // ---- loaders ----
    auto ldg_chunk = [&](int kc) {
        const int k0 = kc * BK;
#pragma unroll
        for (int l = 0; l < 4; l++) {
            int slot = tid + l * 256;      // 0..1023
            int row  = slot >> 3;          // 0..127
            int c4   = slot & 7;           // 0..7
            float4 va = make_float4(0.f, 0.f, 0.f, 0.f);
            if (PAD_A) {
                int m = bm * 128 + row, b = m / NP, t = m - b * NP;
                if (t < NSEQ)
                    va = *(const float4*)&A[((size_t)(b * NSEQ + t)) * DIMC + k0 + c4 * 4];
            } else {
                va = *(const float4*)&A[((size_t)(bm * 128 + row)) * DIMC + k0 + c4 * 4];
            }
            ra[l] = va;
            rb[l] = *(const float4*)&Bt[((size_t)(bn * 128 + row)) * KTOT + k0 + c4 * 4];
        }
    };

    auto split4 = [&](float4 v, uint32_t& h01, uint32_t& h23, uint32_t& l01, uint32_t& l23) {
        __nv_bfloat16 hx = __float2bfloat16_rn(v.x);
        __nv_bfloat16 hy = __float2bfloat16_rn(v.y);
        __nv_bfloat16 hz = __float2bfloat16_rn(v.z);
        __nv_bfloat16 hw = __float2bfloat16_rn(v.w);
        __nv_bfloat16 lx = __float2bfloat16_rn(v.x - __bfloat162float(hx));
        __nv_bfloat16 ly = __float2bfloat16_rn(v.y - __bfloat162float(hy));
        __nv_bfloat16 lz = __float2bfloat16_rn(v.z - __bfloat162float(hz));
        __nv_bfloat16 lw = __float2bfloat16_rn(v.w - __bfloat162float(hw));
        h01 = pack_bf16(hx, hy); h23 = pack_bf16(hz, hw);
        l01 = pack_bf16(lx, ly); l23 = pack_bf16(lz, lw);
    };

    auto sts_chunk = [&](int buf) {
        __nv_bfloat16* Ah = sm + buf * STAGE_ELEMS;
        __nv_bfloat16* Al = Ah + MAT_ELEMS;
        __nv_bfloat16* Bh = Ah + 2 * MAT_ELEMS;
        __nv_bfloat16* Bl = Ah + 3 * MAT_ELEMS;
#pragma unroll
        for (int l = 0; l < 4; l++) {
            int slot = tid + l * 256;
            int row  = slot >> 3;
            int c4   = slot & 7;
            int off  = row * LSTRIDE + c4 * 4;
            uint32_t h01, h23, l01, l23;
            split4(ra[l], h01, h23, l01, l23);
            *(uint32_t*)&Ah[off]     = h01; *(uint32_t*)&Ah[off + 2] = h23;
            *(uint32_t*)&Al[off]     = l01; *(uint32_t*)&Al[off + 2] = l23;
            split4(rb[l], h01, h23, l01, l23);
            *(uint32_t*)&Bh[off]     = h01; *(uint32_t*)&Bh[off + 2] = h23;
            *(uint32_t*)&Bl[off]     = l01; *(uint32_t*)&Bl[off + 2] = l23;
        }
    };

    auto compute = [&](int buf) {
        const __nv_bfloat16* Ah = sm + buf * STAGE_ELEMS;
        const __nv_bfloat16* Al = Ah + MAT_ELEMS;
        const __nv_bfloat16* Bh = Ah + 2 * MAT_ELEMS;
        const __nv_bfloat16* Bl = Ah + 3 * MAT_ELEMS;
#pragma unroll
        for (int ks = 0; ks < 2; ks++) {
            uint32_t afh[4][4], afl[4][4], bfh[4][2], bfl[4][2];
#pragma unroll
            for (int mi = 0; mi < 4; mi++) {
                int r0 = (wm * 64 + mi * 16 + g) * LSTRIDE + ks * 16 + t4 * 2;
                afh[mi][0] = *(const uint32_t*)&Ah[r0];
                afh[mi][1] = *(const uint32_t*)&Ah[r0 + 8 * LSTRIDE];
                afh[mi][2] = *(const uint32_t*)&Ah[r0 + 8];
                afh[mi][3] = *(const uint32_t*)&Ah[r0 + 8 * LSTRIDE + 8];
                afl[mi][0] = *(const uint32_t*)&Al[r0];
                afl[mi][1] = *(const uint32_t*)&Al[r0 + 8 * LSTRIDE];
                afl[mi][2] = *(const uint32_t*)&Al[r0 + 8];
                afl[mi][3] = *(const uint32_t*)&Al[r0 + 8 * LSTRIDE + 8];
            }
#pragma unroll
            for (int ni = 0; ni < 4; ni++) {
                int r0 = (wn * 32 + ni * 8 + g) * LSTRIDE + ks * 16 + t4 * 2;
                bfh[ni][0] = *(const uint32_t*)&Bh[r0];
                bfh[ni][1] = *(const uint32_t*)&Bh[r0 + 8];
                bfl[ni][0] = *(const uint32_t*)&Bl[r0];
                bfl[ni][1] = *(const uint32_t*)&Bl[r0 + 8];
            }
#pragma unroll
            for (int mi = 0; mi < 4; mi++)
#pragma unroll
                for (int ni = 0; ni < 4; ni++) {
                    mma16816(acc[mi][ni], afh[mi], bfh[ni]);
                    mma16816(acc[mi][ni], afh[mi], bfl[ni]);
                    mma16816(acc[mi][ni], afl[mi], bfh[ni]);
                }
        }
    };

    // ---- pipeline ----
    ldg_chunk(0);
    sts_chunk(0);
    __syncthreads();
    for (int kc = 0; kc < NCHUNK; kc++) {
        if (kc + 1 < NCHUNK) ldg_chunk(kc + 1);   // LDGs in flight during MMA
        compute(kc & 1);
        if (kc + 1 < NCHUNK) sts_chunk((kc + 1) & 1);
        __syncthreads();
    }

    // ---- epilogue ----
#pragma unroll
    for (int mi = 0; mi < 4; mi++) {
#pragma unroll
        for (int half = 0; half < 2; half++) {
            int m = bm * 128 + wm * 64 + mi * 16 + g + half * 8;
            float* dst = nullptr;
            if (TRIM) {
                int b = m / NP, t = m - b * NP;
                if (t < NSEQ) dst = &C[((size_t)(b * NSEQ + t)) * NSTRIDE];
            } else {
                dst = &C[(size_t)m * NSTRIDE];
            }
            if (dst) {
                int ncol = bn * 128 + wn * 32 + t4 * 2;
#pragma unroll
                for (int ni = 0; ni < 4; ni++) {
                    float2 v = make_float2(acc[mi][ni][half * 2], acc[mi][ni][half * 2 + 1]);
                    *(float2*)&dst[ncol + ni * 8] = v;
                }
            }
        }
    }
}

// ---------------------------------------------------------------------------
// Text attention: per (b,h), 128 queries x 128 keys, causal.
// ---------------------------------------------------------------------------
__global__ __launch_bounds__(128) void text_attn_kernel()
{
    extern __shared__ float smf[];
    float* KV = smf;
    float* S  = smf + 128 * 64;

    const int bh = blockIdx.x;
    const int b  = bh / NHEAD;
    const int h  = bh - b * NHEAD;
    const int i  = threadIdx.x;

    for (int idx = threadIdx.x; idx < 128 * 64 / 4; idx += 128) {
        int t = idx >> 4, c4 = idx & 15;
        *(float4*)&KV[t * 64 + c4 * 4] =
            *(const float4*)&g_qkv[((size_t)(b * NP + t)) * TRIPLE + DIMC + h * DHEAD + c4 * 4];
    }
    __syncthreads();

    float q[64];
    {
        const float* qp = &g_qkv[((size_t)(b * NP + i)) * TRIPLE + h * DHEAD];
#pragma unroll
        for (int d = 0; d < 64; d++) q[d] = qp[d] * 0.125f;
    }

    float mx = -FLT_MAX;
    for (int j = 0; j <= i; j++) {
        const float* kp = &KV[j * 64];
        float s0 = 0.f, s1 = 0.f, s2 = 0.f, s3 = 0.f;
#pragma unroll
        for (int d = 0; d < 64; d += 4) {
            s0 += q[d+0] * kp[d+0]; s1 += q[d+1] * kp[d+1];
            s2 += q[d+2] * kp[d+2]; s3 += q[d+3] * kp[d+3];
        }
        float s = (s0 + s1) + (s2 + s3);
        S[i * 128 + j] = s;
        mx = fmaxf(mx, s);
    }
    float sum = 0.f;
    for (int j = 0; j <= i; j++) {
        float p = __expf(S[i * 128 + j] - mx);
        S[i * 128 + j] = p;
        sum += p;
    }
    __syncthreads();

    for (int idx = threadIdx.x; idx < 128 * 64 / 4; idx += 128) {
        int t = idx >> 4, c4 = idx & 15;
        *(float4*)&KV[t * 64 + c4 * 4] =
            *(const float4*)&g_qkv[((size_t)(b * NP + t)) * TRIPLE + 2 * DIMC + h * DHEAD + c4 * 4];
    }
    __syncthreads();

    float o[64];
#pragma unroll
    for (int d = 0; d < 64; d++) o[d] = 0.f;
    for (int j = 0; j <= i; j++) {
        float p = S[i * 128 + j];
        const float* vp = &KV[j * 64];
#pragma unroll
        for (int d = 0; d < 64; d++) o[d] += p * vp[d];
    }
    float inv = 1.f / sum;
    float* op = &g_attn[((size_t)(b * NP + i)) * DIMC + h * DHEAD];
#pragma unroll
    for (int d = 0; d < 64; d++) op[d] = o[d] * inv;
}

// ---------------------------------------------------------------------------
// Image (axial) attention: per (b,h,imgrow); 64 queries x (128 text + <=64 row).
// ---------------------------------------------------------------------------
__global__ __launch_bounds__(64) void img_attn_kernel()
{
    extern __shared__ float smf[];
    float* KV = smf;
    float* S  = smf + 192 * 64;
    __shared__ uint8_t smask[TEXTL];

    const int bid = blockIdx.x;
    const int xr  = bid & 63;
    const int h   = (bid >> 6) & 15;
    const int b   = bid >> 10;
    const int i   = threadIdx.x;

    for (int j = threadIdx.x; j < TEXTL; j += 64) smask[j] = g_mask[b * TEXTL + j];

    for (int idx = threadIdx.x; idx < 192 * 64 / 4; idx += 64) {
        int r = idx >> 4, c4 = idx & 15;
        int t = (r < TEXTL) ? r : (TEXTL + xr * 64 + (r - TEXTL));
        *(float4*)&KV[r * 64 + c4 * 4] =
            *(const float4*)&g_qkv[((size_t)(b * NP + t)) * TRIPLE + DIMC + h * DHEAD + c4 * 4];
    }
    __syncthreads();

    float q[64];
    {
        const int tq = TEXTL + xr * 64 + i;
        const float* qp = &g_qkv[((size_t)(b * NP + tq)) * TRIPLE + h * DHEAD];
#pragma unroll
        for (int d = 0; d < 64; d++) q[d] = qp[d] * 0.125f;
    }

    float mx = -FLT_MAX;
    for (int j = 0; j < TEXTL; j++) {
        const float* kp = &KV[j * 64];
        float s0 = 0.f, s1 = 0.f, s2 = 0.f, s3 = 0.f;
#pragma unroll
        for (int d = 0; d < 64; d += 4) {
            s0 += q[d+0] * kp[d+0]; s1 += q[d+1] * kp[d+1];
            s2 += q[d+2] * kp[d+2]; s3 += q[d+3] * kp[d+3];
        }
        float s = (s0 + s1) + (s2 + s3);
        s = smask[j] ? s : -FLT_MAX;
        S[i * 192 + j] = s;
        mx = fmaxf(mx, s);
    }
    for (int j = 0; j <= i; j++) {
        const float* kp = &KV[(TEXTL + j) * 64];
        float s0 = 0.f, s1 = 0.f, s2 = 0.f, s3 = 0.f;
#pragma unroll
        for (int d = 0; d < 64; d += 4) {
            s0 += q[d+0] * kp[d+0]; s1 += q[d+1] * kp[d+1];
            s2 += q[d+2] * kp[d+2]; s3 += q[d+3] * kp[d+3];
        }
        float s = (s0 + s1) + (s2 + s3);
        S[i * 192 + TEXTL + j] = s;
        mx = fmaxf(mx, s);
    }

    float sum = 0.f;
    for (int j = 0; j < TEXTL; j++) {
        float p = __expf(S[i * 192 + j] - mx);
        S[i * 192 + j] = p;
        sum += p;
    }
    for (int j = 0; j <= i; j++) {
        float p = __expf(S[i * 192 + TEXTL + j] - mx);
        S[i * 192 + TEXTL + j] = p;
        sum += p;
    }
    __syncthreads();

    for (int idx = threadIdx.x; idx < 192 * 64 / 4; idx += 64) {
        int r = idx >> 4, c4 = idx & 15;
        int t = (r < TEXTL) ? r : (TEXTL + xr * 64 + (r - TEXTL));
        *(float4*)&KV[r * 64 + c4 * 4] =
            *(const float4*)&g_qkv[((size_t)(b * NP + t)) * TRIPLE + 2 * DIMC + h * DHEAD + c4 * 4];
    }
    __syncthreads();

    float o[64];
#pragma unroll
    for (int d = 0; d < 64; d++) o[d] = 0.f;
    for (int j = 0; j < TEXTL; j++) {
        float p = S[i * 192 + j];
        const float* vp = &KV[j * 64];
#pragma unroll
        for (int d = 0; d < 64; d++) o[d] += p * vp[d];
    }
    for (int j = 0; j <= i; j++) {
        float p = S[i * 192 + TEXTL + j];
        const float* vp = &KV[(TEXTL + j) * 64];
#pragma unroll
        for (int d = 0; d < 64; d++) o[d] += p * vp[d];
    }
    float inv = 1.f / sum;
    const int tq = TEXTL + xr * 64 + i;
    float* op = &g_attn[((size_t)(b * NP + tq)) * DIMC + h * DHEAD];
#pragma unroll
    for (int d = 0; d < 64; d++) op[d] = o[d] * inv;
}

// ---------------------------------------------------------------------------
// Launch
// ---------------------------------------------------------------------------
extern "C" void kernel_launch(void* const* d_in, const int* in_sizes, int n_in,
                              void* d_out, int out_size)
{
    const float* x     = nullptr;
    const void*  mask  = nullptr;
    const float* w_qkv = nullptr;
    const float* w_out = nullptr;
    for (int i = 0; i < n_in; i++) {
        long long sz = in_sizes[i];
        if      (sz == (long long)BATCH * NSEQ * DIMC) x     = (const float*)d_in[i];
        else if (sz == BATCH * TEXTL)                  mask  = d_in[i];
        else if (sz == (long long)DIMC * TRIPLE)       w_qkv = (const float*)d_in[i];
        else if (sz == (long long)DIMC * DIMC)         w_out = (const float*)d_in[i];
    }
    float* out = (float*)d_out;

    float* wt_qkv; cudaGetSymbolAddress((void**)&wt_qkv, g_wt_qkv);
    float* wt_out; cudaGetSymbolAddress((void**)&wt_out, g_wt_out);
    float* attn;   cudaGetSymbolAddress((void**)&attn,   g_attn);
    float* qkv;    cudaGetSymbolAddress((void**)&qkv,    g_qkv);

    const int SMEM_ATT = 98304;
    cudaFuncSetAttribute(text_attn_kernel, cudaFuncAttributeMaxDynamicSharedMemorySize, SMEM_ATT);
    cudaFuncSetAttribute(img_attn_kernel,  cudaFuncAttributeMaxDynamicSharedMemorySize, SMEM_ATT);
    cudaFuncSetAttribute(gemm_mma_kernel<TRIPLE, true,  false>,
                         cudaFuncAttributeMaxDynamicSharedMemorySize, SMEM_GEMM);
    cudaFuncSetAttribute(gemm_mma_kernel<DIMC,   false, true>,
                         cudaFuncAttributeMaxDynamicSharedMemorySize, SMEM_GEMM);

    normalize_mask_kernel<<<1, 256>>>(mask);
    transpose_kernel<<<dim3(TRIPLE / 32, DIMC / 32), dim3(32, 8)>>>(w_qkv, wt_qkv, DIMC, TRIPLE);
    transpose_kernel<<<dim3(DIMC / 32,   DIMC / 32), dim3(32, 8)>>>(w_out, wt_out, DIMC, DIMC);

    dim3 g1(TRIPLE / 128, MROWS / 128);  // 24 x 264
    gemm_mma_kernel<TRIPLE, true, false><<<g1, 256, SMEM_GEMM>>>(x, wt_qkv, qkv);

    text_attn_kernel<<<BATCH * NHEAD, 128, SMEM_ATT>>>();
    img_attn_kernel<<<BATCH * NHEAD * IMGDIM, 64, SMEM_ATT>>>();

    dim3 g2(DIMC / 128, MROWS / 128);    // 8 x 264
    gemm_mma_kernel<DIMC, false, true><<<g2, 256, SMEM_GEMM>>>(attn, wt_out, out);
}